// round 10
// baseline (speedup 1.0000x reference)
#include <cuda_runtime.h>
#include <math.h>

#define B_TOTAL 16384
#define T_LEN   512
#define NSTEP   511
#define HDIM    32
#define WID     64
#define BLK     128
#define GRID    256

typedef unsigned long long u64;

// Tsit5 coefficients
__constant__ float cA[6][5] = {
    {0.f, 0.f, 0.f, 0.f, 0.f},
    {0.161f, 0.f, 0.f, 0.f, 0.f},
    {-0.008480655492356989f, 0.335480655492357f, 0.f, 0.f, 0.f},
    {2.8971530571054935f, -6.359448489975075f, 4.3622954328695815f, 0.f, 0.f},
    {5.325864828439257f, -11.748883564062828f, 7.4955393428898365f, -0.09249506636175525f, 0.f},
    {5.86145544294642f, -12.92096931784711f, 8.159367898576159f, -0.071584973281401f, -0.028269050394068383f}
};
__constant__ float cB[6] = {
    0.09646076681806523f, 0.01f, 0.4798896504144996f,
    1.379008574103742f, -3.290069515436081f, 2.324710524099774f
};

// Transposed, dt-scaled gradient increments: dqT2[(n*3+c)*8192 + e/2] = (dq[e], dq[e+1])
__device__ float2 dqT2[(size_t)NSTEP * 3 * 8192];   // 100.5 MB scratch

// ---- packed f32x2 helpers ----
__device__ __forceinline__ u64 pack2(float lo, float hi) {
    u64 r; asm("mov.b64 %0, {%1, %2};" : "=l"(r) : "f"(lo), "f"(hi)); return r;
}
__device__ __forceinline__ void unpack2(u64 v, float& lo, float& hi) {
    asm("mov.b64 {%0, %1}, %2;" : "=f"(lo), "=f"(hi) : "l"(v));
}
__device__ __forceinline__ u64 dup2(float x) { return pack2(x, x); }
__device__ __forceinline__ u64 fma2(u64 a, u64 b, u64 c) {
    u64 d; asm("fma.rn.f32x2 %0, %1, %2, %3;" : "=l"(d) : "l"(a), "l"(b), "l"(c)); return d;
}

// SMEM layout (floats) — round-7 proven layout
#define OFF_W1T 0                      /* [i=32][j=64] transposed : 2048 */
#define OFF_W2T (OFF_W1T + 2048)       /* [i=64][j=64]            : 4096 */
#define OFF_W3T (OFF_W2T + 4096)       /* [i=64][r=96]            : 6144 */
#define OFF_B1  (OFF_W3T + 6144)       /* 64 */
#define OFF_B2  (OFF_B1 + 64)          /* 64 */
#define OFF_B3  (OFF_B2 + 64)          /* 96 */
#define OFF_Y   (OFF_B3 + 96)          /* u64 [32 comp][32 lane] : 2048 floats */
#define OFF_H1  (OFF_Y + 2048)         /* u64 [64][32] : 4096 */
#define OFF_H2  (OFF_H1 + 4096)        /* u64 [64][32] : 4096 */
#define SMEM_FLOATS (OFF_H2 + 4096)
#define SMEM_BYTES  (SMEM_FLOATS * 4)  /* 91,008 B -> 2 CTAs/SM */

// tanh(x) = 1 - 2/(e^{2x}+1); exact at 0 and +/-inf.
__device__ __forceinline__ float tanh_fast(float x) {
    float e = __expf(2.0f * x);
    float ep1 = e + 1.0f;
    float r; asm("rcp.approx.f32 %0, %1;" : "=f"(r) : "f"(ep1));
    return fmaf(-2.0f, r, 1.0f);
}

// ---- prep kernel: gradients (B,T,3) -> dqT[(n*3+c)*16384 + e], dt folded ----
__global__ void prep_dq(const float* __restrict__ grads,
                        const float* __restrict__ times)
{
    const int e = blockIdx.x * blockDim.x + threadIdx.x;   // 0..16383
    const int t = blockIdx.y;                              // 0..510
    const float dt = times[1] - times[0];
    const float* gp = grads + (size_t)e * T_LEN * 3 + t * 3;
    float v0 = gp[0] * dt;
    float v1 = gp[1] * dt;
    float v2 = gp[2] * dt;
    float* base = (float*)dqT2;
    base[((size_t)t * 3 + 0) * 16384 + e] = v0;   // writes coalesced per plane
    base[((size_t)t * 3 + 1) * 16384 + e] = v1;
    base[((size_t)t * 3 + 2) * 16384 + e] = v2;
}

__global__ void __launch_bounds__(BLK, 2)
neural_cde_kernel(const float* __restrict__ w1g,
                  const float* __restrict__ b1g,
                  const float* __restrict__ w2g,
                  const float* __restrict__ b2g,
                  const float* __restrict__ w3g,
                  const float* __restrict__ b3g,
                  const float* __restrict__ wencg,
                  const float* __restrict__ bencg,
                  const float* __restrict__ wrog,
                  const float* __restrict__ brog,
                  float* __restrict__ out)
{
    extern __shared__ float sm[];
    float* w1t  = sm + OFF_W1T;
    float* w2t  = sm + OFF_W2T;
    float* w3t  = sm + OFF_W3T;
    float* b1s  = sm + OFF_B1;
    float* b2s  = sm + OFF_B2;
    float* b3s  = sm + OFF_B3;
    u64*   ysm  = (u64*)(sm + OFF_Y);
    u64*   h1sm = (u64*)(sm + OFF_H1);
    u64*   h2sm = (u64*)(sm + OFF_H2);

    const int tid  = threadIdx.x;
    const int w    = tid >> 5;
    const int lane = tid & 31;

    // ---- stage weights (transposed) ----
    for (int idx = tid; idx < 2048; idx += BLK) {        // w1: [64][32] -> w1t[i][j]
        int j = idx >> 5, i = idx & 31;
        w1t[i * 64 + j] = w1g[idx];
    }
    for (int idx = tid; idx < 4096; idx += BLK) {        // w2: [64][64] -> w2t[i][j]
        int j = idx >> 6, i = idx & 63;
        w2t[i * 64 + j] = w2g[idx];
    }
    for (int idx = tid; idx < 6144; idx += BLK) {        // w3: [96][64] -> w3t[i][r]
        int r = idx >> 6, i = idx & 63;
        w3t[i * 96 + r] = w3g[idx];
    }
    for (int idx = tid; idx < 64; idx += BLK) b1s[idx] = b1g[idx];
    for (int idx = tid; idx < 64; idx += BLK) b2s[idx] = b2g[idx];
    for (int idx = tid; idx < 96; idx += BLK) b3s[idx] = b3g[idx];
    __syncthreads();

    const int g = blockIdx.x;
    // adjacent pairing: elemA = g*64 + 2*lane, elemB = elemA + 1
    const int pidx = g * 32 + lane;     // float2 index within each (n,c) plane

    // packed per-thread state: comps [8w,8w+8), halves = (elemA, elemB)
    u64 zp[8], k0p[8], k1p[8], k2p[8], k3p[8], k4p[8], kvp[8];
#pragma unroll
    for (int p = 0; p < 8; p++) {
        int c = 8 * w + p;
        zp[p] = dup2(wencg[c] + bencg[c]);
        k0p[p] = k1p[p] = k2p[p] = k3p[p] = k4p[p] = 0ull;
    }

    const u64 bw0 = dup2(cB[0]), bw1 = dup2(cB[1]), bw2 = dup2(cB[2]);
    const u64 bw3 = dup2(cB[3]), bw4 = dup2(cB[4]), bw5 = dup2(cB[5]);

    // prefetch step 0's dq (float2 = (dqA, dqB))
    float2 nd0 = dqT2[(size_t)0 * 8192 + pidx];
    float2 nd1 = dqT2[(size_t)1 * 8192 + pidx];
    float2 nd2 = dqT2[(size_t)2 * 8192 + pidx];

#pragma unroll 1
    for (int n = 0; n < NSTEP; n++) {
        const float dqA0 = nd0.x, dqB0 = nd0.y;
        const float dqA1 = nd1.x, dqB1 = nd1.y;
        const float dqA2 = nd2.x, dqB2 = nd2.y;

        // prefetch next step (clamped reload at the end; values unused)
        const int np = (n + 1 < NSTEP) ? n + 1 : n;
        nd0 = dqT2[((size_t)np * 3 + 0) * 8192 + pidx];
        nd1 = dqT2[((size_t)np * 3 + 1) * 8192 + pidx];
        nd2 = dqT2[((size_t)np * 3 + 2) * 8192 + pidx];

#pragma unroll 1
        for (int s = 0; s < 6; s++) {
            const u64 a0 = dup2(cA[s][0]), a1 = dup2(cA[s][1]);
            const u64 a2 = dup2(cA[s][2]), a3 = dup2(cA[s][3]);
            const u64 a4 = dup2(cA[s][4]);

            // phase 1: y slice -> smem (zero coeffs are exact no-ops)
#pragma unroll
            for (int p = 0; p < 8; p++) {
                u64 acc = zp[p];
                acc = fma2(a0, k0p[p], acc);
                acc = fma2(a1, k1p[p], acc);
                acc = fma2(a2, k2p[p], acc);
                acc = fma2(a3, k3p[p], acc);
                acc = fma2(a4, k4p[p], acc);
                ysm[(8 * w + p) * 32 + lane] = acc;
            }
            __syncthreads();

            // phase 2: L1 rows [16w,16w+16)
            {
                u64 accA[8], accB[8];
                const u64* bp = (const u64*)(b1s + 16 * w);
#pragma unroll
                for (int u = 0; u < 8; u++) { accA[u] = bp[u]; accB[u] = bp[u]; }
#pragma unroll 8
                for (int i = 0; i < HDIM; i++) {
                    float yA, yB;
                    unpack2(ysm[i * 32 + lane], yA, yB);
                    const u64 dA = dup2(yA), dB = dup2(yB);
                    const ulonglong2* wp = (const ulonglong2*)(w1t + i * 64 + 16 * w);
#pragma unroll
                    for (int q = 0; q < 4; q++) {
                        ulonglong2 wq = wp[q];
                        accA[2 * q + 0] = fma2(wq.x, dA, accA[2 * q + 0]);
                        accA[2 * q + 1] = fma2(wq.y, dA, accA[2 * q + 1]);
                        accB[2 * q + 0] = fma2(wq.x, dB, accB[2 * q + 0]);
                        accB[2 * q + 1] = fma2(wq.y, dB, accB[2 * q + 1]);
                    }
                }
#pragma unroll
                for (int u = 0; u < 8; u++) {
                    float aA0, aA1, aB0, aB1;
                    unpack2(accA[u], aA0, aA1);
                    unpack2(accB[u], aB0, aB1);
                    int r0 = 16 * w + 2 * u;
                    h1sm[r0 * 32 + lane]       = pack2(tanh_fast(aA0), tanh_fast(aB0));
                    h1sm[(r0 + 1) * 32 + lane] = pack2(tanh_fast(aA1), tanh_fast(aB1));
                }
            }
            __syncthreads();

            // phase 3: L2 rows [16w,16w+16)
            {
                u64 accA[8], accB[8];
                const u64* bp = (const u64*)(b2s + 16 * w);
#pragma unroll
                for (int u = 0; u < 8; u++) { accA[u] = bp[u]; accB[u] = bp[u]; }
#pragma unroll 8
                for (int i = 0; i < WID; i++) {
                    float hA, hB;
                    unpack2(h1sm[i * 32 + lane], hA, hB);
                    const u64 dA = dup2(hA), dB = dup2(hB);
                    const ulonglong2* wp = (const ulonglong2*)(w2t + i * 64 + 16 * w);
#pragma unroll
                    for (int q = 0; q < 4; q++) {
                        ulonglong2 wq = wp[q];
                        accA[2 * q + 0] = fma2(wq.x, dA, accA[2 * q + 0]);
                        accA[2 * q + 1] = fma2(wq.y, dA, accA[2 * q + 1]);
                        accB[2 * q + 0] = fma2(wq.x, dB, accB[2 * q + 0]);
                        accB[2 * q + 1] = fma2(wq.y, dB, accB[2 * q + 1]);
                    }
                }
#pragma unroll
                for (int u = 0; u < 8; u++) {
                    float aA0, aA1, aB0, aB1;
                    unpack2(accA[u], aA0, aA1);
                    unpack2(accB[u], aB0, aB1);
                    int r0 = 16 * w + 2 * u;
                    h2sm[r0 * 32 + lane]       = pack2(tanh_fast(aA0), tanh_fast(aB0));
                    h2sm[(r0 + 1) * 32 + lane] = pack2(tanh_fast(aA1), tanh_fast(aB1));
                }
            }
            __syncthreads();

            // phase 4: L3 rows [24w,24w+24) + dq contraction
            {
                u64 accA[12], accB[12];
                const u64* bp = (const u64*)(b3s + 24 * w);
#pragma unroll
                for (int u = 0; u < 12; u++) { accA[u] = bp[u]; accB[u] = bp[u]; }
#pragma unroll 8
                for (int i = 0; i < WID; i++) {
                    float hA, hB;
                    unpack2(h2sm[i * 32 + lane], hA, hB);
                    const u64 dA = dup2(hA), dB = dup2(hB);
                    const ulonglong2* wp = (const ulonglong2*)(w3t + i * 96 + 24 * w);
#pragma unroll
                    for (int q = 0; q < 6; q++) {
                        ulonglong2 wq = wp[q];
                        accA[2 * q + 0] = fma2(wq.x, dA, accA[2 * q + 0]);
                        accA[2 * q + 1] = fma2(wq.y, dA, accA[2 * q + 1]);
                        accB[2 * q + 0] = fma2(wq.x, dB, accB[2 * q + 0]);
                        accB[2 * q + 1] = fma2(wq.y, dB, accB[2 * q + 1]);
                    }
                }
                float fA[24], fB[24];
#pragma unroll
                for (int u = 0; u < 12; u++) {
                    unpack2(accA[u], fA[2 * u], fA[2 * u + 1]);
                    unpack2(accB[u], fB[2 * u], fB[2 * u + 1]);
                }
#pragma unroll
                for (int p = 0; p < 8; p++) {
                    float kA = fA[3 * p] * dqA0;
                    kA = fmaf(fA[3 * p + 1], dqA1, kA);
                    kA = fmaf(fA[3 * p + 2], dqA2, kA);
                    float kB = fB[3 * p] * dqB0;
                    kB = fmaf(fB[3 * p + 1], dqB1, kB);
                    kB = fmaf(fB[3 * p + 2], dqB2, kB);
                    kvp[p] = pack2(kA, kB);
                }
            }

            if (s == 0) {
#pragma unroll
                for (int p = 0; p < 8; p++) k0p[p] = kvp[p];
            } else if (s == 1) {
#pragma unroll
                for (int p = 0; p < 8; p++) k1p[p] = kvp[p];
            } else if (s == 2) {
#pragma unroll
                for (int p = 0; p < 8; p++) k2p[p] = kvp[p];
            } else if (s == 3) {
#pragma unroll
                for (int p = 0; p < 8; p++) k3p[p] = kvp[p];
            } else if (s == 4) {
#pragma unroll
                for (int p = 0; p < 8; p++) k4p[p] = kvp[p];
            }
        } // stages

#pragma unroll
        for (int p = 0; p < 8; p++) {
            u64 acc = fma2(bw5, kvp[p], zp[p]);
            acc = fma2(bw0, k0p[p], acc);
            acc = fma2(bw1, k1p[p], acc);
            acc = fma2(bw2, k2p[p], acc);
            acc = fma2(bw3, k3p[p], acc);
            acc = fma2(bw4, k4p[p], acc);
            zp[p] = acc;
        }
    } // steps

    // readout: per-warp partial dots, reduce via smem; coalesced float2 output
    {
        float partA = 0.0f, partB = 0.0f;
#pragma unroll
        for (int p = 0; p < 8; p++) {
            float zA, zB;
            unpack2(zp[p], zA, zB);
            float wr = wrog[8 * w + p];
            partA = fmaf(zA, wr, partA);
            partB = fmaf(zB, wr, partB);
        }
        float* red = (float*)ysm;  // 256 floats scratch
        red[w * 32 + lane]       = partA;
        red[128 + w * 32 + lane] = partB;
        __syncthreads();
        if (tid < 32) {
            int l = tid;
            float b0 = brog[0];
            float logitA = red[l] + red[32 + l] + red[64 + l] + red[96 + l] + b0;
            float logitB = red[128 + l] + red[160 + l] + red[192 + l] + red[224 + l] + b0;
            float sA = __fdividef(1.0f, 1.0f + __expf(-logitA));
            float sB = __fdividef(1.0f, 1.0f + __expf(-logitB));
            ((float2*)out)[g * 32 + l] = make_float2(sA, sB);
        }
    }
}

extern "C" void kernel_launch(void* const* d_in, const int* in_sizes, int n_in,
                              void* d_out, int out_size)
{
    const float* times = (const float*)d_in[0];
    const float* grads = (const float*)d_in[1];
    const float* w1    = (const float*)d_in[2];
    const float* b1    = (const float*)d_in[3];
    const float* w2    = (const float*)d_in[4];
    const float* b2    = (const float*)d_in[5];
    const float* w3    = (const float*)d_in[6];
    const float* b3    = (const float*)d_in[7];
    const float* wenc  = (const float*)d_in[8];
    const float* benc  = (const float*)d_in[9];
    const float* wro   = (const float*)d_in[10];
    const float* bro   = (const float*)d_in[11];
    float* out = (float*)d_out;

    // 1) transpose + dt-fold gradients into dqT planes
    dim3 pgrid(B_TOTAL / 256, NSTEP);
    prep_dq<<<pgrid, 256>>>(grads, times);

    // 2) main kernel (round-7 proven core + coalesced dq streaming)
    cudaFuncSetAttribute(neural_cde_kernel,
                         cudaFuncAttributeMaxDynamicSharedMemorySize, SMEM_BYTES);
    neural_cde_kernel<<<GRID, BLK, SMEM_BYTES>>>(
        w1, b1, w2, b2, w3, b3, wenc, benc, wro, bro, out);
}

// round 11
// speedup vs baseline: 1.5555x; 1.5555x over previous
#include <cuda_runtime.h>
#include <math.h>

#define B_TOTAL 16384
#define T_LEN   512
#define NSTEP   511
#define HDIM    32
#define WID     64
#define BLK     256
#define GRID    256          /* 256 CTAs x 64 elements */

typedef unsigned long long u64;

// Tsit5 coefficients
__constant__ float cA[6][5] = {
    {0.f, 0.f, 0.f, 0.f, 0.f},
    {0.161f, 0.f, 0.f, 0.f, 0.f},
    {-0.008480655492356989f, 0.335480655492357f, 0.f, 0.f, 0.f},
    {2.8971530571054935f, -6.359448489975075f, 4.3622954328695815f, 0.f, 0.f},
    {5.325864828439257f, -11.748883564062828f, 7.4955393428898365f, -0.09249506636175525f, 0.f},
    {5.86145544294642f, -12.92096931784711f, 8.159367898576159f, -0.071584973281401f, -0.028269050394068383f}
};
__constant__ float cB[6] = {
    0.09646076681806523f, 0.01f, 0.4798896504144996f,
    1.379008574103742f, -3.290069515436081f, 2.324710524099774f
};

// Transposed, dt-scaled gradient increments, adjacent-pair layout:
// plane (n,c): float2[(n*3+c)*8192 + e/2] = (dq[e], dq[e+1])
__device__ float2 dqT2[(size_t)NSTEP * 3 * 8192];   // 100.5 MB scratch

// ---- packed f32x2 helpers ----
__device__ __forceinline__ u64 pack2(float lo, float hi) {
    u64 r; asm("mov.b64 %0, {%1, %2};" : "=l"(r) : "f"(lo), "f"(hi)); return r;
}
__device__ __forceinline__ void unpack2(u64 v, float& lo, float& hi) {
    asm("mov.b64 {%0, %1}, %2;" : "=f"(lo), "=f"(hi) : "l"(v));
}
__device__ __forceinline__ u64 dup2(float x) { return pack2(x, x); }
__device__ __forceinline__ u64 fma2(u64 a, u64 b, u64 c) {
    u64 d; asm("fma.rn.f32x2 %0, %1, %2, %3;" : "=l"(d) : "l"(a), "l"(b), "l"(c)); return d;
}

// SMEM layout (floats)
#define OFF_W1T 0                      /* [i=32][j=64] transposed : 2048 */
#define OFF_W2T (OFF_W1T + 2048)       /* [i=64][j=64]            : 4096 */
#define OFF_W3T (OFF_W2T + 4096)       /* [i=64][8 warps][16 pad] : 8192 */
#define OFF_B1  (OFF_W3T + 8192)       /* 64 */
#define OFF_B2  (OFF_B1 + 64)          /* 64 */
#define OFF_B3  (OFF_B2 + 64)          /* 96 */
#define OFF_Y   (OFF_B3 + 96)          /* u64 [32 comp][32 lane] : 2048 floats */
#define OFF_H1  (OFF_Y + 2048)         /* u64 [64][32] : 4096 */
#define OFF_H2  (OFF_H1 + 4096)        /* u64 [64][32] : 4096 */
#define SMEM_FLOATS (OFF_H2 + 4096)
#define SMEM_BYTES  (SMEM_FLOATS * 4)  /* 99,200 B -> 2 CTAs/SM (198 KB) */

// tanh(x) = 1 - 2/(e^{2x}+1); exact at 0 and +/-inf.
__device__ __forceinline__ float tanh_fast(float x) {
    float e = __expf(2.0f * x);
    float ep1 = e + 1.0f;
    float r; asm("rcp.approx.f32 %0, %1;" : "=f"(r) : "f"(ep1));
    return fmaf(-2.0f, r, 1.0f);
}

// ---- prep kernel: gradients (B,T,3) -> dqT planes, dt folded ----
__global__ void prep_dq(const float* __restrict__ grads,
                        const float* __restrict__ times)
{
    const int e = blockIdx.x * blockDim.x + threadIdx.x;   // 0..16383
    const int t = blockIdx.y;                              // 0..510
    const float dt = times[1] - times[0];
    const float* gp = grads + (size_t)e * T_LEN * 3 + t * 3;
    float v0 = gp[0] * dt;
    float v1 = gp[1] * dt;
    float v2 = gp[2] * dt;
    float* base = (float*)dqT2;
    base[((size_t)t * 3 + 0) * 16384 + e] = v0;
    base[((size_t)t * 3 + 1) * 16384 + e] = v1;
    base[((size_t)t * 3 + 2) * 16384 + e] = v2;
}

__global__ void __launch_bounds__(BLK, 2)
neural_cde_kernel(const float* __restrict__ w1g,
                  const float* __restrict__ b1g,
                  const float* __restrict__ w2g,
                  const float* __restrict__ b2g,
                  const float* __restrict__ w3g,
                  const float* __restrict__ b3g,
                  const float* __restrict__ wencg,
                  const float* __restrict__ bencg,
                  const float* __restrict__ wrog,
                  const float* __restrict__ brog,
                  float* __restrict__ out)
{
    extern __shared__ float sm[];
    float* w1t  = sm + OFF_W1T;
    float* w2t  = sm + OFF_W2T;
    float* w3t  = sm + OFF_W3T;
    float* b1s  = sm + OFF_B1;
    float* b2s  = sm + OFF_B2;
    float* b3s  = sm + OFF_B3;
    u64*   ysm  = (u64*)(sm + OFF_Y);
    u64*   h1sm = (u64*)(sm + OFF_H1);
    u64*   h2sm = (u64*)(sm + OFF_H2);

    const int tid  = threadIdx.x;
    const int w    = tid >> 5;     // warp = row-slice 0..7
    const int lane = tid & 31;     // lane = element pair within group

    // ---- stage weights (transposed) ----
    for (int idx = tid; idx < 2048; idx += BLK) {        // w1: [64][32] -> w1t[i][j]
        int j = idx >> 5, i = idx & 31;
        w1t[i * 64 + j] = w1g[idx];
    }
    for (int idx = tid; idx < 4096; idx += BLK) {        // w2: [64][64] -> w2t[i][j]
        int j = idx >> 6, i = idx & 63;
        w2t[i * 64 + j] = w2g[idx];
    }
    for (int idx = tid; idx < 6144; idx += BLK) {        // w3: [96][64] -> padded slices
        int r = idx >> 6, i = idx & 63;
        w3t[i * 128 + (r / 12) * 16 + (r % 12)] = w3g[idx];
    }
    for (int idx = tid; idx < 64; idx += BLK) b1s[idx] = b1g[idx];
    for (int idx = tid; idx < 64; idx += BLK) b2s[idx] = b2g[idx];
    for (int idx = tid; idx < 96; idx += BLK) b3s[idx] = b3g[idx];
    __syncthreads();

    const int g = blockIdx.x;
    const int pidx = g * 32 + lane;     // float2 index within each (n,c) plane

    // per-thread state: comps [4w, 4w+4), halves = (elemA=2*lane, elemB=2*lane+1)
    u64 zp[4], k0p[4], k1p[4], k2p[4], k3p[4], k4p[4], kvp[4];
#pragma unroll
    for (int p = 0; p < 4; p++) {
        int c = 4 * w + p;
        zp[p] = dup2(wencg[c] + bencg[c]);
        k0p[p] = k1p[p] = k2p[p] = k3p[p] = k4p[p] = 0ull;
    }

    const u64 bw0 = dup2(cB[0]), bw1 = dup2(cB[1]), bw2 = dup2(cB[2]);
    const u64 bw3 = dup2(cB[3]), bw4 = dup2(cB[4]), bw5 = dup2(cB[5]);

#pragma unroll 1
    for (int n = 0; n < NSTEP; n++) {
        // coalesced dq loads; consumed in phase 4 (hidden under phases 1-3)
        const float2 nd0 = dqT2[((size_t)n * 3 + 0) * 8192 + pidx];
        const float2 nd1 = dqT2[((size_t)n * 3 + 1) * 8192 + pidx];
        const float2 nd2 = dqT2[((size_t)n * 3 + 2) * 8192 + pidx];

#pragma unroll 1
        for (int s = 0; s < 6; s++) {
            const u64 a0 = dup2(cA[s][0]), a1 = dup2(cA[s][1]);
            const u64 a2 = dup2(cA[s][2]), a3 = dup2(cA[s][3]);
            const u64 a4 = dup2(cA[s][4]);

            // phase 1: y slice -> smem (zero coeffs are exact no-ops)
#pragma unroll
            for (int p = 0; p < 4; p++) {
                u64 acc = zp[p];
                acc = fma2(a0, k0p[p], acc);
                acc = fma2(a1, k1p[p], acc);
                acc = fma2(a2, k2p[p], acc);
                acc = fma2(a3, k3p[p], acc);
                acc = fma2(a4, k4p[p], acc);
                ysm[(4 * w + p) * 32 + lane] = acc;
            }
            __syncthreads();

            // phase 2: L1 rows [8w, 8w+8)
            {
                u64 accA[4], accB[4];
                const u64* bp = (const u64*)(b1s + 8 * w);
#pragma unroll
                for (int u = 0; u < 4; u++) { accA[u] = bp[u]; accB[u] = bp[u]; }
#pragma unroll 8
                for (int i = 0; i < HDIM; i++) {
                    float yA, yB;
                    unpack2(ysm[i * 32 + lane], yA, yB);
                    const u64 dA = dup2(yA), dB = dup2(yB);
                    const ulonglong2* wp = (const ulonglong2*)(w1t + i * 64 + 8 * w);
#pragma unroll
                    for (int q = 0; q < 2; q++) {
                        ulonglong2 wq = wp[q];
                        accA[2 * q + 0] = fma2(wq.x, dA, accA[2 * q + 0]);
                        accA[2 * q + 1] = fma2(wq.y, dA, accA[2 * q + 1]);
                        accB[2 * q + 0] = fma2(wq.x, dB, accB[2 * q + 0]);
                        accB[2 * q + 1] = fma2(wq.y, dB, accB[2 * q + 1]);
                    }
                }
#pragma unroll
                for (int u = 0; u < 4; u++) {
                    float aA0, aA1, aB0, aB1;
                    unpack2(accA[u], aA0, aA1);
                    unpack2(accB[u], aB0, aB1);
                    int r0 = 8 * w + 2 * u;
                    h1sm[r0 * 32 + lane]       = pack2(tanh_fast(aA0), tanh_fast(aB0));
                    h1sm[(r0 + 1) * 32 + lane] = pack2(tanh_fast(aA1), tanh_fast(aB1));
                }
            }
            __syncthreads();

            // phase 3: L2 rows [8w, 8w+8)
            {
                u64 accA[4], accB[4];
                const u64* bp = (const u64*)(b2s + 8 * w);
#pragma unroll
                for (int u = 0; u < 4; u++) { accA[u] = bp[u]; accB[u] = bp[u]; }
#pragma unroll 8
                for (int i = 0; i < WID; i++) {
                    float hA, hB;
                    unpack2(h1sm[i * 32 + lane], hA, hB);
                    const u64 dA = dup2(hA), dB = dup2(hB);
                    const ulonglong2* wp = (const ulonglong2*)(w2t + i * 64 + 8 * w);
#pragma unroll
                    for (int q = 0; q < 2; q++) {
                        ulonglong2 wq = wp[q];
                        accA[2 * q + 0] = fma2(wq.x, dA, accA[2 * q + 0]);
                        accA[2 * q + 1] = fma2(wq.y, dA, accA[2 * q + 1]);
                        accB[2 * q + 0] = fma2(wq.x, dB, accB[2 * q + 0]);
                        accB[2 * q + 1] = fma2(wq.y, dB, accB[2 * q + 1]);
                    }
                }
#pragma unroll
                for (int u = 0; u < 4; u++) {
                    float aA0, aA1, aB0, aB1;
                    unpack2(accA[u], aA0, aA1);
                    unpack2(accB[u], aB0, aB1);
                    int r0 = 8 * w + 2 * u;
                    h2sm[r0 * 32 + lane]       = pack2(tanh_fast(aA0), tanh_fast(aB0));
                    h2sm[(r0 + 1) * 32 + lane] = pack2(tanh_fast(aA1), tanh_fast(aB1));
                }
            }
            __syncthreads();

            // phase 4: L3 rows [12w, 12w+12) + dq contraction
            {
                u64 accA[6], accB[6];
                const u64* bp = (const u64*)(b3s + 12 * w);   // 48w bytes, 8B-aligned
#pragma unroll
                for (int u = 0; u < 6; u++) { accA[u] = bp[u]; accB[u] = bp[u]; }
#pragma unroll 8
                for (int i = 0; i < WID; i++) {
                    float hA, hB;
                    unpack2(h2sm[i * 32 + lane], hA, hB);
                    const u64 dA = dup2(hA), dB = dup2(hB);
                    // padded slice: 16 floats per warp -> 64B, 16B-aligned
                    const ulonglong2* wp = (const ulonglong2*)(w3t + i * 128 + 16 * w);
#pragma unroll
                    for (int q = 0; q < 3; q++) {
                        ulonglong2 wq = wp[q];
                        accA[2 * q + 0] = fma2(wq.x, dA, accA[2 * q + 0]);
                        accA[2 * q + 1] = fma2(wq.y, dA, accA[2 * q + 1]);
                        accB[2 * q + 0] = fma2(wq.x, dB, accB[2 * q + 0]);
                        accB[2 * q + 1] = fma2(wq.y, dB, accB[2 * q + 1]);
                    }
                }
                float fA[12], fB[12];
#pragma unroll
                for (int u = 0; u < 6; u++) {
                    unpack2(accA[u], fA[2 * u], fA[2 * u + 1]);
                    unpack2(accB[u], fB[2 * u], fB[2 * u + 1]);
                }
#pragma unroll
                for (int p = 0; p < 4; p++) {
                    float kA = fA[3 * p] * nd0.x;
                    kA = fmaf(fA[3 * p + 1], nd1.x, kA);
                    kA = fmaf(fA[3 * p + 2], nd2.x, kA);
                    float kB = fB[3 * p] * nd0.y;
                    kB = fmaf(fB[3 * p + 1], nd1.y, kB);
                    kB = fmaf(fB[3 * p + 2], nd2.y, kB);
                    kvp[p] = pack2(kA, kB);
                }
            }

            if (s == 0) {
#pragma unroll
                for (int p = 0; p < 4; p++) k0p[p] = kvp[p];
            } else if (s == 1) {
#pragma unroll
                for (int p = 0; p < 4; p++) k1p[p] = kvp[p];
            } else if (s == 2) {
#pragma unroll
                for (int p = 0; p < 4; p++) k2p[p] = kvp[p];
            } else if (s == 3) {
#pragma unroll
                for (int p = 0; p < 4; p++) k3p[p] = kvp[p];
            } else if (s == 4) {
#pragma unroll
                for (int p = 0; p < 4; p++) k4p[p] = kvp[p];
            }
        } // stages

#pragma unroll
        for (int p = 0; p < 4; p++) {
            u64 acc = fma2(bw5, kvp[p], zp[p]);
            acc = fma2(bw0, k0p[p], acc);
            acc = fma2(bw1, k1p[p], acc);
            acc = fma2(bw2, k2p[p], acc);
            acc = fma2(bw3, k3p[p], acc);
            acc = fma2(bw4, k4p[p], acc);
            zp[p] = acc;
        }
    } // steps

    // readout: 8 per-warp partial dots, reduce via smem; coalesced float2 out
    {
        float partA = 0.0f, partB = 0.0f;
#pragma unroll
        for (int p = 0; p < 4; p++) {
            float zA, zB;
            unpack2(zp[p], zA, zB);
            float wr = wrog[4 * w + p];
            partA = fmaf(zA, wr, partA);
            partB = fmaf(zB, wr, partB);
        }
        float* red = (float*)ysm;  // 512 floats scratch
        red[w * 32 + lane]        = partA;
        red[256 + w * 32 + lane]  = partB;
        __syncthreads();
        if (tid < 32) {
            int l = tid;
            float b0 = brog[0];
            float logitA = 0.0f, logitB = 0.0f;
#pragma unroll
            for (int q = 0; q < 8; q++) {
                logitA += red[q * 32 + l];
                logitB += red[256 + q * 32 + l];
            }
            logitA += b0;
            logitB += b0;
            float sA = __fdividef(1.0f, 1.0f + __expf(-logitA));
            float sB = __fdividef(1.0f, 1.0f + __expf(-logitB));
            ((float2*)out)[g * 32 + l] = make_float2(sA, sB);
        }
    }
}

extern "C" void kernel_launch(void* const* d_in, const int* in_sizes, int n_in,
                              void* d_out, int out_size)
{
    const float* times = (const float*)d_in[0];
    const float* grads = (const float*)d_in[1];
    const float* w1    = (const float*)d_in[2];
    const float* b1    = (const float*)d_in[3];
    const float* w2    = (const float*)d_in[4];
    const float* b2    = (const float*)d_in[5];
    const float* w3    = (const float*)d_in[6];
    const float* b3    = (const float*)d_in[7];
    const float* wenc  = (const float*)d_in[8];
    const float* benc  = (const float*)d_in[9];
    const float* wro   = (const float*)d_in[10];
    const float* bro   = (const float*)d_in[11];
    float* out = (float*)d_out;

    // 1) transpose + dt-fold gradients into coalesced planes
    dim3 pgrid(B_TOTAL / 256, NSTEP);
    prep_dq<<<pgrid, 256>>>(grads, times);

    // 2) main kernel: 8-warp row-split, 16 warps/SM
    cudaFuncSetAttribute(neural_cde_kernel,
                         cudaFuncAttributeMaxDynamicSharedMemorySize, SMEM_BYTES);
    neural_cde_kernel<<<GRID, BLK, SMEM_BYTES>>>(
        w1, b1, w2, b2, w3, b3, wenc, benc, wro, bro, out);
}